// round 3
// baseline (speedup 1.0000x reference)
#include <cuda_runtime.h>
#include <cuda_bf16.h>

#ifndef D
#define D 128
#endif

__global__ __launch_bounds__(128, 8) void sgns_kernel3(
    const int*   __restrict__ x,        // [BS, 1, 3] int32
    const float* __restrict__ tgt_base, // [VOCAB, 128]
    const float* __restrict__ tgt_a,    // [SIDE, 128]
    const float* __restrict__ tgt_b,    // [SIDE, 128]
    const float* __restrict__ ctx_base, // [VOCAB, 128]
    const float* __restrict__ ctx_a,    // [SIDE, 128]
    const float* __restrict__ ctx_b,    // [SIDE, 128]
    const float* __restrict__ tgt_w,    // [3,1]
    const float* __restrict__ ctx_w,    // [3,1]
    float*       __restrict__ out,      // [BS]
    int bs)
{
    const int warp = (blockIdx.x * blockDim.x + threadIdx.x) >> 5;
    const int lane = threadIdx.x & 31;
    const int r0 = warp * 2;
    if (r0 >= bs) return;

    // 6 indices for the 2 rows as 3x int2 (8B-aligned: base + 24B*warp)
    const int2 xa = __ldg((const int2*)(x + (size_t)warp * 6) + 0);
    const int2 xb = __ldg((const int2*)(x + (size_t)warp * 6) + 1);
    const int2 xc = __ldg((const int2*)(x + (size_t)warp * 6) + 2);
    const int a0 = xa.x, a1 = xa.y, a2 = xb.x;
    const int b0 = xb.y, b1 = xc.x, b2 = xc.y;

    // 12 independent 16B gathers — all issued before dependent math (MLP=12)
    const float4 t0b = __ldg((const float4*)(tgt_base + (size_t)a0 * D) + lane);
    const float4 t0a = __ldg((const float4*)(tgt_a    + (size_t)a1 * D) + lane);
    const float4 t0c = __ldg((const float4*)(tgt_b    + (size_t)a2 * D) + lane);
    const float4 c0b = __ldg((const float4*)(ctx_base + (size_t)a0 * D) + lane);
    const float4 c0a = __ldg((const float4*)(ctx_a    + (size_t)a1 * D) + lane);
    const float4 c0c = __ldg((const float4*)(ctx_b    + (size_t)a2 * D) + lane);

    const float4 t1b = __ldg((const float4*)(tgt_base + (size_t)b0 * D) + lane);
    const float4 t1a = __ldg((const float4*)(tgt_a    + (size_t)b1 * D) + lane);
    const float4 t1c = __ldg((const float4*)(tgt_b    + (size_t)b2 * D) + lane);
    const float4 c1b = __ldg((const float4*)(ctx_base + (size_t)b0 * D) + lane);
    const float4 c1a = __ldg((const float4*)(ctx_a    + (size_t)b1 * D) + lane);
    const float4 c1c = __ldg((const float4*)(ctx_b    + (size_t)b2 * D) + lane);

    // softmax(tgt_w), softmax(ctx_w) — overlaps with gather latency
    float tw0 = __ldg(&tgt_w[0]), tw1 = __ldg(&tgt_w[1]), tw2 = __ldg(&tgt_w[2]);
    float tm  = fmaxf(tw0, fmaxf(tw1, tw2));
    float te0 = __expf(tw0 - tm), te1 = __expf(tw1 - tm), te2 = __expf(tw2 - tm);
    float tinv = __frcp_rn(te0 + te1 + te2);
    float w0 = te0 * tinv, w1 = te1 * tinv, w2 = te2 * tinv;

    float cw0 = __ldg(&ctx_w[0]), cw1 = __ldg(&ctx_w[1]), cw2 = __ldg(&ctx_w[2]);
    float cm  = fmaxf(cw0, fmaxf(cw1, cw2));
    float ce0 = __expf(cw0 - cm), ce1 = __expf(cw1 - cm), ce2 = __expf(cw2 - cm);
    float cinv = __frcp_rn(ce0 + ce1 + ce2);
    float v0 = ce0 * cinv, v1 = ce1 * cinv, v2 = ce2 * cinv;

    float tx, cx, p0, p1;
    // row 0
    tx = w0 * t0b.x + w1 * t0a.x + w2 * t0c.x;
    cx = v0 * c0b.x + v1 * c0a.x + v2 * c0c.x;
    p0 = tx * cx;
    tx = w0 * t0b.y + w1 * t0a.y + w2 * t0c.y;
    cx = v0 * c0b.y + v1 * c0a.y + v2 * c0c.y;
    p0 += tx * cx;
    tx = w0 * t0b.z + w1 * t0a.z + w2 * t0c.z;
    cx = v0 * c0b.z + v1 * c0a.z + v2 * c0c.z;
    p0 += tx * cx;
    tx = w0 * t0b.w + w1 * t0a.w + w2 * t0c.w;
    cx = v0 * c0b.w + v1 * c0a.w + v2 * c0c.w;
    p0 += tx * cx;

    // row 1
    tx = w0 * t1b.x + w1 * t1a.x + w2 * t1c.x;
    cx = v0 * c1b.x + v1 * c1a.x + v2 * c1c.x;
    p1 = tx * cx;
    tx = w0 * t1b.y + w1 * t1a.y + w2 * t1c.y;
    cx = v0 * c1b.y + v1 * c1a.y + v2 * c1c.y;
    p1 += tx * cx;
    tx = w0 * t1b.z + w1 * t1a.z + w2 * t1c.z;
    cx = v0 * c1b.z + v1 * c1a.z + v2 * c1c.z;
    p1 += tx * cx;
    tx = w0 * t1b.w + w1 * t1a.w + w2 * t1c.w;
    cx = v0 * c1b.w + v1 * c1a.w + v2 * c1c.w;
    p1 += tx * cx;

    // warp reduction — two chains pipeline through the SHFL latency
    #pragma unroll
    for (int off = 16; off > 0; off >>= 1) {
        p0 += __shfl_xor_sync(0xFFFFFFFFu, p0, off);
        p1 += __shfl_xor_sync(0xFFFFFFFFu, p1, off);
    }

    if (lane == 0) {
        float s0 = __frcp_rn(1.0f + __expf(-p0));
        float s1 = __frcp_rn(1.0f + __expf(-p1));
        if (r0 + 1 < bs) {
            *(float2*)(out + r0) = make_float2(s0, s1);
        } else {
            out[r0] = s0;
        }
    }
}

extern "C" void kernel_launch(void* const* d_in, const int* in_sizes, int n_in,
                              void* d_out, int out_size)
{
    const int*   x        = (const int*)  d_in[0];
    const float* tgt_base = (const float*)d_in[1];
    const float* tgt_a    = (const float*)d_in[2];
    const float* tgt_b    = (const float*)d_in[3];
    const float* ctx_base = (const float*)d_in[4];
    const float* ctx_a    = (const float*)d_in[5];
    const float* ctx_b    = (const float*)d_in[6];
    const float* tgt_w    = (const float*)d_in[7];
    const float* ctx_w    = (const float*)d_in[8];
    float* out = (float*)d_out;

    const int bs = in_sizes[0] / 3;
    const int threads = 128;                 // 4 warps/block -> fine occupancy quantization
    const int rows_per_block = (threads / 32) * 2;
    const int blocks = (bs + rows_per_block - 1) / rows_per_block;

    sgns_kernel3<<<blocks, threads>>>(x, tgt_base, tgt_a, tgt_b,
                                      ctx_base, ctx_a, ctx_b,
                                      tgt_w, ctx_w, out, bs);
}

// round 4
// speedup vs baseline: 1.4963x; 1.4963x over previous
#include <cuda_runtime.h>
#include <cuda_bf16.h>

#ifndef D
#define D 128
#endif

// NOTE: no max-blocks clamp — round 3 proved capping regs to 64 forces spills
// (12 live float4 ≈ 48 data regs + addressing). Let ptxas use ~70 regs;
// occupancy comes from the 64-thread block quantization instead.
__global__ __launch_bounds__(64) void sgns_kernel4(
    const int*   __restrict__ x,        // [BS, 1, 3] int32
    const float* __restrict__ tgt_base, // [VOCAB, 128]
    const float* __restrict__ tgt_a,    // [SIDE, 128]
    const float* __restrict__ tgt_b,    // [SIDE, 128]
    const float* __restrict__ ctx_base, // [VOCAB, 128]
    const float* __restrict__ ctx_a,    // [SIDE, 128]
    const float* __restrict__ ctx_b,    // [SIDE, 128]
    const float* __restrict__ tgt_w,    // [3,1]
    const float* __restrict__ ctx_w,    // [3,1]
    float*       __restrict__ out,      // [BS]
    int bs)
{
    const int warp = (blockIdx.x * blockDim.x + threadIdx.x) >> 5;
    const int lane = threadIdx.x & 31;
    const int r0 = warp * 2;
    if (r0 >= bs) return;

    // 6 indices for the 2 rows as 3x int2 (8B-aligned: base + 24B*warp)
    const int2 xa = __ldg((const int2*)(x + (size_t)warp * 6) + 0);
    const int2 xb = __ldg((const int2*)(x + (size_t)warp * 6) + 1);
    const int2 xc = __ldg((const int2*)(x + (size_t)warp * 6) + 2);
    const int a0 = xa.x, a1 = xa.y, a2 = xb.x;
    const int b0 = xb.y, b1 = xc.x, b2 = xc.y;

    // 12 independent 16B gathers — all issued before dependent math (MLP=12)
    const float4 t0b = __ldg((const float4*)(tgt_base + (size_t)a0 * D) + lane);
    const float4 t0a = __ldg((const float4*)(tgt_a    + (size_t)a1 * D) + lane);
    const float4 t0c = __ldg((const float4*)(tgt_b    + (size_t)a2 * D) + lane);
    const float4 c0b = __ldg((const float4*)(ctx_base + (size_t)a0 * D) + lane);
    const float4 c0a = __ldg((const float4*)(ctx_a    + (size_t)a1 * D) + lane);
    const float4 c0c = __ldg((const float4*)(ctx_b    + (size_t)a2 * D) + lane);

    const float4 t1b = __ldg((const float4*)(tgt_base + (size_t)b0 * D) + lane);
    const float4 t1a = __ldg((const float4*)(tgt_a    + (size_t)b1 * D) + lane);
    const float4 t1c = __ldg((const float4*)(tgt_b    + (size_t)b2 * D) + lane);
    const float4 c1b = __ldg((const float4*)(ctx_base + (size_t)b0 * D) + lane);
    const float4 c1a = __ldg((const float4*)(ctx_a    + (size_t)b1 * D) + lane);
    const float4 c1c = __ldg((const float4*)(ctx_b    + (size_t)b2 * D) + lane);

    // softmax(tgt_w), softmax(ctx_w) — overlaps with gather latency
    float tw0 = __ldg(&tgt_w[0]), tw1 = __ldg(&tgt_w[1]), tw2 = __ldg(&tgt_w[2]);
    float tm  = fmaxf(tw0, fmaxf(tw1, tw2));
    float te0 = __expf(tw0 - tm), te1 = __expf(tw1 - tm), te2 = __expf(tw2 - tm);
    float tinv = __frcp_rn(te0 + te1 + te2);
    float w0 = te0 * tinv, w1 = te1 * tinv, w2 = te2 * tinv;

    float cw0 = __ldg(&ctx_w[0]), cw1 = __ldg(&ctx_w[1]), cw2 = __ldg(&ctx_w[2]);
    float cm  = fmaxf(cw0, fmaxf(cw1, cw2));
    float ce0 = __expf(cw0 - cm), ce1 = __expf(cw1 - cm), ce2 = __expf(cw2 - cm);
    float cinv = __frcp_rn(ce0 + ce1 + ce2);
    float v0 = ce0 * cinv, v1 = ce1 * cinv, v2 = ce2 * cinv;

    float tx, cx, p0, p1;
    // row 0
    tx = w0 * t0b.x + w1 * t0a.x + w2 * t0c.x;
    cx = v0 * c0b.x + v1 * c0a.x + v2 * c0c.x;
    p0 = tx * cx;
    tx = w0 * t0b.y + w1 * t0a.y + w2 * t0c.y;
    cx = v0 * c0b.y + v1 * c0a.y + v2 * c0c.y;
    p0 += tx * cx;
    tx = w0 * t0b.z + w1 * t0a.z + w2 * t0c.z;
    cx = v0 * c0b.z + v1 * c0a.z + v2 * c0c.z;
    p0 += tx * cx;
    tx = w0 * t0b.w + w1 * t0a.w + w2 * t0c.w;
    cx = v0 * c0b.w + v1 * c0a.w + v2 * c0c.w;
    p0 += tx * cx;

    // row 1
    tx = w0 * t1b.x + w1 * t1a.x + w2 * t1c.x;
    cx = v0 * c1b.x + v1 * c1a.x + v2 * c1c.x;
    p1 = tx * cx;
    tx = w0 * t1b.y + w1 * t1a.y + w2 * t1c.y;
    cx = v0 * c1b.y + v1 * c1a.y + v2 * c1c.y;
    p1 += tx * cx;
    tx = w0 * t1b.z + w1 * t1a.z + w2 * t1c.z;
    cx = v0 * c1b.z + v1 * c1a.z + v2 * c1c.z;
    p1 += tx * cx;
    tx = w0 * t1b.w + w1 * t1a.w + w2 * t1c.w;
    cx = v0 * c1b.w + v1 * c1a.w + v2 * c1c.w;
    p1 += tx * cx;

    // warp reduction — two chains pipeline through the SHFL latency
    #pragma unroll
    for (int off = 16; off > 0; off >>= 1) {
        p0 += __shfl_xor_sync(0xFFFFFFFFu, p0, off);
        p1 += __shfl_xor_sync(0xFFFFFFFFu, p1, off);
    }

    if (lane == 0) {
        float s0 = __frcp_rn(1.0f + __expf(-p0));
        float s1 = __frcp_rn(1.0f + __expf(-p1));
        if (r0 + 1 < bs) {
            *(float2*)(out + r0) = make_float2(s0, s1);
        } else {
            out[r0] = s0;
        }
    }
}

extern "C" void kernel_launch(void* const* d_in, const int* in_sizes, int n_in,
                              void* d_out, int out_size)
{
    const int*   x        = (const int*)  d_in[0];
    const float* tgt_base = (const float*)d_in[1];
    const float* tgt_a    = (const float*)d_in[2];
    const float* tgt_b    = (const float*)d_in[3];
    const float* ctx_base = (const float*)d_in[4];
    const float* ctx_a    = (const float*)d_in[5];
    const float* ctx_b    = (const float*)d_in[6];
    const float* tgt_w    = (const float*)d_in[7];
    const float* ctx_w    = (const float*)d_in[8];
    float* out = (float*)d_out;

    const int bs = in_sizes[0] / 3;
    const int threads = 64;                  // 2 warps/block -> 14 blocks/SM at 70 regs
    const int rows_per_block = (threads / 32) * 2;
    const int blocks = (bs + rows_per_block - 1) / rows_per_block;

    sgns_kernel4<<<blocks, threads>>>(x, tgt_base, tgt_a, tgt_b,
                                      ctx_base, ctx_a, ctx_b,
                                      tgt_w, ctx_w, out, bs);
}